// round 5
// baseline (speedup 1.0000x reference)
#include <cuda_runtime.h>

// ARModel p=1, C=1, out_dim=1:
//   out[b,t,n] = (t==0) ? 0 : x[b,t-1,n] * w + bias
// Flat over float4: out4[i] = x4[i - N4]*w + bias unless t(i)==0 (then 0).
//
// R3: cache-policy fix. Reads are .cs (evict-first, streamed once, don't
// pollute L2). Stores are DEFAULT .wb — dirty output lines linger in L2 and
// get re-dirtied by the next graph replay without draining to DRAM, cutting
// DRAM write traffic. (R2's .stcs stores forced writes out of L2 early.)

#define AR_B 64
#define AR_T 288
#define AR_N 2000
#define AR_N4 (AR_N / 4)                       // 500
#define AR_TOTAL4 (AR_B * AR_T * AR_N4)        // 9,216,000
#define AR_UNROLL 4
#define AR_THREADS 256
#define AR_BLOCKS (AR_TOTAL4 / (AR_THREADS * AR_UNROLL))   // 9000 exact
#define AR_STRIDE (AR_BLOCKS * AR_THREADS)                 // 2,304,000

__global__ __launch_bounds__(AR_THREADS) void ar_model_kernel(
    const float4* __restrict__ x4,
    const float* __restrict__ w_ptr,
    const float* __restrict__ b_ptr,
    float4* __restrict__ out4)
{
    int base = blockIdx.x * AR_THREADS + threadIdx.x;

    const float W  = __ldg(w_ptr);
    const float Bi = __ldg(b_ptr);

    int   idx[AR_UNROLL];
    bool  live[AR_UNROLL];
    float4 v[AR_UNROLL];

    // Front-batch all loads: 4 independent LDG.128 in flight per thread.
    #pragma unroll
    for (int u = 0; u < AR_UNROLL; u++) {
        int i = base + u * AR_STRIDE;
        idx[u] = i;
        int row = i / AR_N4;           // (b*T + t)
        int t   = row % AR_T;
        live[u] = (t != 0);
        if (live[u]) {
            v[u] = __ldcs(&x4[i - AR_N4]);   // streaming read, evict-first
        }
    }

    #pragma unroll
    for (int u = 0; u < AR_UNROLL; u++) {
        float4 o;
        if (live[u]) {
            o.x = fmaf(v[u].x, W, Bi);
            o.y = fmaf(v[u].y, W, Bi);
            o.z = fmaf(v[u].z, W, Bi);
            o.w = fmaf(v[u].w, W, Bi);
        } else {
            o.x = 0.0f; o.y = 0.0f; o.z = 0.0f; o.w = 0.0f;
        }
        out4[idx[u]] = o;                    // default .wb store — stay in L2
    }
}

extern "C" void kernel_launch(void* const* d_in, const int* in_sizes, int n_in,
                              void* d_out, int out_size)
{
    const float4* x4 = (const float4*)d_in[0];
    const float*  w  = (const float*)d_in[1];
    const float*  b  = (const float*)d_in[2];
    float4* out4 = (float4*)d_out;

    ar_model_kernel<<<AR_BLOCKS, AR_THREADS>>>(x4, w, b, out4);
}

// round 6
// speedup vs baseline: 1.0374x; 1.0374x over previous
#include <cuda_runtime.h>

// ARModel p=1, C=1, out_dim=1:
//   out[b,t,n] = (t==0) ? 0 : x[b,t-1,n] * w + bias
// Flat over float4: out4[i] = x4[i - N4]*w + bias unless t(i)==0 (then 0).
//
// R5: back to R2's proven cache policy (.cs on BOTH read and store — zero
// reuse, evict-first everywhere; R3 showed .wb stores hurt). Unroll 4 -> 8
// front-batched LDG.128 per thread to raise per-warp MLP (latency exposure
// is the residual: DRAM 77%, issue 15%).

#define AR_B 64
#define AR_T 288
#define AR_N 2000
#define AR_N4 (AR_N / 4)                       // 500
#define AR_TOTAL4 (AR_B * AR_T * AR_N4)        // 9,216,000
#define AR_UNROLL 8
#define AR_THREADS 256
#define AR_BLOCKS (AR_TOTAL4 / (AR_THREADS * AR_UNROLL))   // 4500 exact
#define AR_STRIDE (AR_BLOCKS * AR_THREADS)                 // 1,152,000

__global__ __launch_bounds__(AR_THREADS) void ar_model_kernel(
    const float4* __restrict__ x4,
    const float* __restrict__ w_ptr,
    const float* __restrict__ b_ptr,
    float4* __restrict__ out4)
{
    int base = blockIdx.x * AR_THREADS + threadIdx.x;

    const float W  = __ldg(w_ptr);
    const float Bi = __ldg(b_ptr);

    bool   live[AR_UNROLL];
    float4 v[AR_UNROLL];

    // Front-batch all loads: 8 independent LDG.128 in flight per thread.
    #pragma unroll
    for (int u = 0; u < AR_UNROLL; u++) {
        int i = base + u * AR_STRIDE;
        int row = i / AR_N4;           // (b*T + t)
        int t   = row % AR_T;
        live[u] = (t != 0);
        if (live[u]) {
            v[u] = __ldcs(&x4[i - AR_N4]);   // streaming read, evict-first
        }
    }

    #pragma unroll
    for (int u = 0; u < AR_UNROLL; u++) {
        float4 o;
        if (live[u]) {
            o.x = fmaf(v[u].x, W, Bi);
            o.y = fmaf(v[u].y, W, Bi);
            o.z = fmaf(v[u].z, W, Bi);
            o.w = fmaf(v[u].w, W, Bi);
        } else {
            o.x = 0.0f; o.y = 0.0f; o.z = 0.0f; o.w = 0.0f;
        }
        __stcs(&out4[base + u * AR_STRIDE], o);  // streaming write, evict-first
    }
}

extern "C" void kernel_launch(void* const* d_in, const int* in_sizes, int n_in,
                              void* d_out, int out_size)
{
    const float4* x4 = (const float4*)d_in[0];
    const float*  w  = (const float*)d_in[1];
    const float*  b  = (const float*)d_in[2];
    float4* out4 = (float4*)d_out;

    ar_model_kernel<<<AR_BLOCKS, AR_THREADS>>>(x4, w, b, out4);
}